// round 12
// baseline (speedup 1.0000x reference)
#include <cuda_runtime.h>
#include <math.h>

#define NN 16800
#define KK 1024
#define BB 64
#define NT 1024
#define HP 257
#define SVMAX 6144

struct SF {
    union {
        struct {                              // select phase
            unsigned okey[NN];                // 67200 B
            unsigned hist32[32 * HP];         // 32896 B
            unsigned long long surv[SVMAX];   // 49152 B
            unsigned hist256[256];
        } a;
        struct {                              // nms phase
            float4 sbox[KK];
            float  sarea[KK];
            float  sval[KK];
            unsigned long long smask[KK];     // intra-chunk row masks
            float  skpt[KK * 10];
        } n;
    } u;
    unsigned long long cand[KK];
    unsigned long long skept[16];
    unsigned salive[32];
    int ready[16];
    int pub;
    unsigned warpsum[8];
    unsigned pref_arr[5];
    int kr_arr[5];
    int wsum[32];
    int cntgt;
    int svcnt;
    int eqtot;
};

// exact-equivalent IoU>0.3 test (bit-identical decisions to __fdiv_rn(...)>0.3f)
__device__ __forceinline__ bool iou_gt(float inter, float den) {
    if (inter > 0.301f * den) return true;
    if (inter > 0.299f * den) return __fdiv_rn(inter, den) > 0.3f;
    return false;
}

__global__ __launch_bounds__(NT, 1)
void k_fused(const float* __restrict__ p_loc,
             const float* __restrict__ p_conf,
             const float* __restrict__ p_landms,
             const float* __restrict__ anchors,
             float* __restrict__ out)
{
    extern __shared__ char raw[];
    SF* s = reinterpret_cast<SF*>(raw);
    const int b = blockIdx.x, tid = threadIdx.x;
    const int lane = tid & 31, wrp = tid >> 5;
    const float* conf = p_conf + (size_t)b * NN;

    if (tid == 0) { s->pref_arr[0] = 0u; s->kr_arr[0] = KK; s->cntgt = 0; s->svcnt = 0; s->eqtot = 0; s->pub = 0; }
    if (tid < 16) s->ready[tid] = 0;

    // ================= pass 0: 8-bit top byte, per-warp histograms =================
    for (int t = tid; t < 32 * HP; t += NT) s->u.a.hist32[t] = 0u;
    __syncthreads();
    for (int base = 0; base < NN; base += NT) {
        int i = base + tid;
        bool v = (i < NN);
        unsigned ok = 0u;
        if (v) {
            float c = conf[i];
            ok = (c >= 0.0f) ? (__float_as_uint(c) | 0x80000000u) : 0u;
            s->u.a.okey[i] = ok;
        }
        unsigned bucket = v ? (ok >> 24) : 0xFFFFFFFFu;
        unsigned grp = __match_any_sync(0xffffffffu, bucket);
        if (v && lane == (__ffs(grp) - 1))
            s->u.a.hist32[wrp * HP + bucket] += (unsigned)__popc(grp);
    }
    __syncthreads();
    {   // digit find (threads 0..255 own buckets)
        unsigned cnt = 0, ssum = 0;
        if (tid < 256) {
            #pragma unroll
            for (int w = 0; w < 32; w++) cnt += s->u.a.hist32[w * HP + tid];
            ssum = cnt;
            #pragma unroll
            for (int d = 1; d < 32; d <<= 1) {
                unsigned x = __shfl_down_sync(0xffffffffu, ssum, d);
                if (lane + d < 32) ssum += x;
            }
            if (lane == 0) s->warpsum[wrp] = ssum;
        }
        __syncthreads();
        if (tid < 256) {
            unsigned hi = 0;
            for (int w = wrp + 1; w < 8; w++) hi += s->warpsum[w];
            unsigned S = ssum + hi;
            if (S >= (unsigned)KK && S - cnt < (unsigned)KK) {
                s->pref_arr[1] = (unsigned)tid;
                s->kr_arr[1] = KK - (int)(S - cnt);
                s->eqtot = (int)cnt;
            }
        }
        __syncthreads();
    }

    const int E0 = s->eqtot;
    const unsigned d0 = s->pref_arr[1];
    bool compacted = false;

    if (E0 <= SVMAX) {
        // compact: top byte > d0 -> cand (order-free); == d0 -> surv
        for (int base = 0; base < NN; base += NT) {
            int i = base + tid;
            bool v = (i < NN);
            unsigned ok = v ? s->u.a.okey[i] : 0u;
            bool gt = v && ((ok >> 24) > d0);
            bool eq = v && ((ok >> 24) == d0);
            unsigned balg = __ballot_sync(0xffffffffu, gt);
            int pg = 0;
            if (lane == 0 && balg) pg = atomicAdd(&s->cntgt, __popc(balg));
            pg = __shfl_sync(0xffffffffu, pg, 0);
            if (gt) s->cand[pg + __popc(balg & ((1u << lane) - 1u))] =
                        (((unsigned long long)ok) << 32) | (unsigned)(~(unsigned)i);
            unsigned bale = __ballot_sync(0xffffffffu, eq);
            int pe = 0;
            if (lane == 0 && bale) pe = atomicAdd(&s->svcnt, __popc(bale));
            pe = __shfl_sync(0xffffffffu, pe, 0);
            if (eq) s->u.a.surv[pe + __popc(bale & ((1u << lane) - 1u))] =
                        (((unsigned long long)ok) << 32) | (unsigned)(~(unsigned)i);
        }
        __syncthreads();
        const int svn = s->svcnt;
        const int iters = (svn + NT - 1) / NT;

        // passes 1..3 over survivors
        for (int p = 1; p < 4; p++) {
            const int shift = 24 - 8 * p;
            if (tid < 256) s->u.a.hist256[tid] = 0u;
            __syncthreads();
            const unsigned prefv = s->pref_arr[p];
            const int krloc = s->kr_arr[p];
            for (int it = 0; it < iters; it++) {
                int ix = it * NT + tid;
                bool valid = (ix < svn);
                unsigned key = valid ? (unsigned)(s->u.a.surv[ix] >> 32) : 0u;
                bool part = valid && ((key >> (shift + 8)) == prefv);
                unsigned bucket = part ? ((key >> shift) & 255u) : 0xFFFFFFFFu;
                unsigned grp = __match_any_sync(0xffffffffu, bucket);
                if (part && lane == (__ffs(grp) - 1))
                    atomicAdd(&s->u.a.hist256[bucket], (unsigned)__popc(grp));
            }
            __syncthreads();
            unsigned cnt = 0, ssum = 0;
            if (tid < 256) {
                cnt = s->u.a.hist256[tid];
                ssum = cnt;
                #pragma unroll
                for (int d = 1; d < 32; d <<= 1) {
                    unsigned x = __shfl_down_sync(0xffffffffu, ssum, d);
                    if (lane + d < 32) ssum += x;
                }
                if (lane == 0) s->warpsum[wrp] = ssum;
            }
            __syncthreads();
            if (tid < 256) {
                unsigned hi = 0;
                for (int w = wrp + 1; w < 8; w++) hi += s->warpsum[w];
                unsigned S = ssum + hi;
                if (S >= (unsigned)krloc && S - cnt < (unsigned)krloc) {
                    s->pref_arr[p + 1] = (prefv << 8) | (unsigned)tid;
                    s->kr_arr[p + 1] = krloc - (int)(S - cnt);
                    s->eqtot = (int)cnt;
                }
            }
            __syncthreads();
        }

        if (s->eqtot == s->kr_arr[4]) {
            const unsigned T = s->pref_arr[4];
            for (int it = 0; it < iters; it++) {
                int ix = it * NT + tid;
                bool valid = (ix < svn);
                unsigned long long sv = valid ? s->u.a.surv[ix] : 0ull;
                bool take = valid && ((unsigned)(sv >> 32) >= T);
                unsigned bal = __ballot_sync(0xffffffffu, take);
                int pg = 0;
                if (lane == 0 && bal) pg = atomicAdd(&s->cntgt, __popc(bal));
                pg = __shfl_sync(0xffffffffu, pg, 0);
                if (take) s->cand[pg + __popc(bal & ((1u << lane) - 1u))] = sv;
            }
            compacted = true;
            __syncthreads();
        }
    } else {
        // full-scan passes 1..3
        for (int p = 1; p < 4; p++) {
            const int shift = 24 - 8 * p;
            for (int t = tid; t < 32 * HP; t += NT) s->u.a.hist32[t] = 0u;
            __syncthreads();
            const unsigned prefv = s->pref_arr[p];
            const int krloc = s->kr_arr[p];
            for (int base = 0; base < NN; base += NT) {
                int i = base + tid;
                bool v = (i < NN);
                unsigned ok = v ? s->u.a.okey[i] : 0u;
                bool part = v && ((ok >> (shift + 8)) == prefv);
                unsigned bucket = part ? ((ok >> shift) & 255u) : 0xFFFFFFFFu;
                unsigned grp = __match_any_sync(0xffffffffu, bucket);
                if (part && lane == (__ffs(grp) - 1))
                    s->u.a.hist32[wrp * HP + bucket] += (unsigned)__popc(grp);
            }
            __syncthreads();
            unsigned cnt = 0, ssum = 0;
            if (tid < 256) {
                #pragma unroll
                for (int w = 0; w < 32; w++) cnt += s->u.a.hist32[w * HP + tid];
                ssum = cnt;
                #pragma unroll
                for (int d = 1; d < 32; d <<= 1) {
                    unsigned x = __shfl_down_sync(0xffffffffu, ssum, d);
                    if (lane + d < 32) ssum += x;
                }
                if (lane == 0) s->warpsum[wrp] = ssum;
            }
            __syncthreads();
            if (tid < 256) {
                unsigned hi = 0;
                for (int w = wrp + 1; w < 8; w++) hi += s->warpsum[w];
                unsigned S = ssum + hi;
                if (S >= (unsigned)krloc && S - cnt < (unsigned)krloc) {
                    s->pref_arr[p + 1] = (prefv << 8) | (unsigned)tid;
                    s->kr_arr[p + 1] = krloc - (int)(S - cnt);
                    s->eqtot = (int)cnt;
                }
            }
            __syncthreads();
        }
        if (s->eqtot == s->kr_arr[4] && s->pref_arr[4] != 0u) {
            const unsigned T = s->pref_arr[4];
            if (tid == 0) s->cntgt = 0;
            __syncthreads();
            int mycnt = 0;
            for (int base = 0; base < NN; base += NT) {
                int i = base + tid;
                bool take = (i < NN) && (s->u.a.okey[i] >= T);
                mycnt += __popc(__ballot_sync(0xffffffffu, take));
            }
            int wb = 0;
            if (lane == 0) wb = atomicAdd(&s->cntgt, mycnt);
            wb = __shfl_sync(0xffffffffu, wb, 0);
            for (int base = 0; base < NN; base += NT) {
                int i = base + tid;
                bool take = (i < NN) && (s->u.a.okey[i] >= T);
                unsigned bal = __ballot_sync(0xffffffffu, take);
                if (take) {
                    int pos = wb + __popc(bal & ((1u << lane) - 1u));
                    s->cand[pos] = (((unsigned long long)s->u.a.okey[i]) << 32) | (unsigned)(~(unsigned)i);
                }
                wb += __popc(bal);
            }
            compacted = true;
            __syncthreads();
        }
    }

    // stable fallback (rare: ties beyond cutoff or T==0)
    if (!compacted) {
        const unsigned T = s->pref_arr[4];
        const int need = s->kr_arr[4];
        const int eq0 = KK - need;
        __syncthreads();
        if (tid == 0) s->cntgt = 0;
        __syncthreads();
        int eqbase = 0;
        for (int base = 0; base < NN; base += NT) {
            int i = base + tid;
            bool v = (i < NN);
            unsigned ok = v ? s->u.a.okey[i] : 0u;
            bool gt = v && (ok > T);
            bool eq = v && (ok == T);
            if (gt) {
                int p2 = atomicAdd(&s->cntgt, 1);
                s->cand[p2] = (((unsigned long long)ok) << 32) | (unsigned)(~(unsigned)i);
            }
            unsigned bal = __ballot_sync(0xffffffffu, eq);
            if (lane == 0) s->wsum[wrp] = __popc(bal);
            __syncthreads();
            int woff = 0, tot = 0;
            #pragma unroll
            for (int w = 0; w < 32; w++) { int x = s->wsum[w]; if (w < wrp) woff += x; tot += x; }
            int rank = eqbase + woff + __popc(bal & ((1u << lane) - 1u));
            if (eq && rank < need)
                s->cand[eq0 + rank] = (((unsigned long long)T) << 32) | (unsigned)(~(unsigned)i);
            eqbase += tot;
            __syncthreads();
        }
    }

    // ===== bitonic sort descending; warp-local shfl phases for j<=16 =====
    {   // k2 = 2..32 fully warp-local
        unsigned long long v = s->cand[tid];
        #pragma unroll
        for (int k2 = 2; k2 <= 32; k2 <<= 1) {
            #pragma unroll
            for (int j = k2 >> 1; j >= 1; j >>= 1) {
                unsigned long long pv = __shfl_xor_sync(0xffffffffu, v, j);
                bool keepMax = ((tid & k2) == 0) == ((tid & j) == 0);
                v = keepMax ? (v > pv ? v : pv) : (v < pv ? v : pv);
            }
        }
        s->cand[tid] = v;
    }
    __syncthreads();
    for (int k2 = 64; k2 <= KK; k2 <<= 1) {
        for (int j = k2 >> 1; j >= 32; j >>= 1) {
            int ixj = tid ^ j;
            if (ixj > tid) {
                unsigned long long a = s->cand[tid], cc = s->cand[ixj];
                bool sw = ((tid & k2) == 0) ? (a < cc) : (a > cc);
                if (sw) { s->cand[tid] = cc; s->cand[ixj] = a; }
            }
            __syncthreads();
        }
        unsigned long long v = s->cand[tid];
        #pragma unroll
        for (int j = 16; j >= 1; j >>= 1) {
            unsigned long long pv = __shfl_xor_sync(0xffffffffu, v, j);
            bool keepMax = ((tid & k2) == 0) == ((tid & j) == 0);
            v = keepMax ? (v > pv ? v : pv) : (v < pv ? v : pv);
        }
        s->cand[tid] = v;
        __syncthreads();
    }

    // ================= gather + decode into smem (union .n) =================
    float4 bj; float aj;
    bool alive;
    {
        int t = tid;
        unsigned long long cd = s->cand[t];
        int idx = (int)(~(unsigned)cd);
        unsigned ok = (unsigned)(cd >> 32);
        float c = __uint_as_float(ok & 0x7FFFFFFFu);
        float vj = (ok != 0u) ? (1.0f / (1.0f + expf(-c))) : -1.0f;
        alive = (ok != 0u);
        float4 a = ((const float4*)anchors)[idx];
        float4 l = ((const float4*)p_loc)[(size_t)b * NN + idx];
        float cx = a.x + l.x * 0.1f * a.z;
        float cy = a.y + l.y * 0.1f * a.w;
        float w = a.z * expf(l.z * 0.2f);
        float h = a.w * expf(l.w * 0.2f);
        float x1 = cx - w * 0.5f, y1 = cy - h * 0.5f;
        float x2 = cx + w * 0.5f, y2 = cy + h * 0.5f;
        bj = make_float4(x1, y1, x2, y2);
        aj = fmaxf(x2 - x1, 0.0f) * fmaxf(y2 - y1, 0.0f);
        s->u.n.sbox[t] = bj;
        s->u.n.sarea[t] = aj;
        s->u.n.sval[t] = vj;
        const float2* lm2 = (const float2*)(p_landms + ((size_t)b * NN + idx) * 10);
        #pragma unroll
        for (int p2 = 0; p2 < 5; p2++) {
            float2 d = lm2[p2];
            s->u.n.skpt[t * 10 + 2 * p2]     = a.x + d.x * 0.1f * a.z;
            s->u.n.skpt[t * 10 + 2 * p2 + 1] = a.y + d.y * 0.1f * a.w;
        }
    }
    __syncthreads();

    // ================= Phase A: intra-chunk 64x64 suppression masks =================
    {
        int t64 = tid & 63, base = tid & ~63;
        unsigned long long m = 0ull;
        for (int j = t64 + 1; j < 64; j++) {
            float4 bq = s->u.n.sbox[base + j];
            float  aq = s->u.n.sarea[base + j];
            float lx = fmaxf(bj.x, bq.x);
            float ly = fmaxf(bj.y, bq.y);
            float rx = fminf(bj.z, bq.z);
            float ry = fminf(bj.w, bq.w);
            float ww = fmaxf(rx - lx, 0.0f);
            float hh = fmaxf(ry - ly, 0.0f);
            if (ww > 0.0f && hh > 0.0f) {
                float inter = ww * hh;
                float den = aj + aq - inter + 1e-9f;
                if (iou_gt(inter, den)) m |= (1ull << j);
            }
        }
        s->u.n.smask[tid] = m;
    }
    __syncthreads();

    // ========== Phase B: pipelined scan/apply (no block barriers) ==========
    // warp w owns rows 32w..32w+31 (chunk w/2). warp 0 is the scanner.
    volatile int* vpub = &s->pub;
    volatile int* vready = s->ready;
    volatile unsigned* vsalive = s->salive;

    if (wrp == 0) {
        for (int c = 0; c < 16; c++) {
            int target = (c == 0) ? 1 : 2;
            while (vready[c] < target) { }
            unsigned long long a;
            if (c == 0) {
                unsigned blo = __ballot_sync(0xffffffffu, alive);
                a = (unsigned long long)blo | ((unsigned long long)vsalive[1] << 32);
            } else {
                a = (unsigned long long)vsalive[2 * c]
                  | ((unsigned long long)vsalive[2 * c + 1] << 32);
            }
            unsigned long long dlo = s->u.n.smask[c * 64 + lane];
            unsigned long long dhi = s->u.n.smask[c * 64 + 32 + lane];
            unsigned long long kept = 0ull;
            while (a) {
                int t = __ffsll((long long)a) - 1;
                kept |= (1ull << t);
                unsigned long long mrow = (t < 32)
                    ? __shfl_sync(0xffffffffu, dlo, t)
                    : __shfl_sync(0xffffffffu, dhi, t - 32);
                a &= ~(mrow | (1ull << t));
            }
            if (lane == 0) {
                s->skept[c] = kept;
                __threadfence_block();
                *vpub = c + 1;
            }
            __syncwarp();
        }
    } else {
        const int cw = wrp >> 1;   // my chunk
        for (int j = 0; j < cw; j++) {
            if (__ballot_sync(0xffffffffu, alive) == 0u) break;
            while (*vpub <= j) { }
            unsigned long long k = s->skept[j];
            while (k) {
                int t = __ffsll((long long)k) - 1;
                k &= k - 1;
                int pi = j * 64 + t;
                float4 bi = s->u.n.sbox[pi];
                float  ai = s->u.n.sarea[pi];
                if (alive) {
                    float lx = fmaxf(bi.x, bj.x);
                    float ly = fmaxf(bi.y, bj.y);
                    float rx = fminf(bi.z, bj.z);
                    float ry = fminf(bi.w, bj.w);
                    float ww = fmaxf(rx - lx, 0.0f);
                    float hh = fmaxf(ry - ly, 0.0f);
                    if (ww > 0.0f && hh > 0.0f) {
                        float inter = ww * hh;
                        float den = ai + aj - inter + 1e-9f;
                        if (iou_gt(inter, den)) alive = false;
                    }
                }
                if (__ballot_sync(0xffffffffu, alive) == 0u) break;
            }
        }
        unsigned bal = __ballot_sync(0xffffffffu, alive);
        if (lane == 0) {
            s->salive[wrp] = bal;
            __threadfence_block();
            atomicAdd(&s->ready[cw], 1);
        }
    }
    __syncthreads();

    // ===== masked output: [ltrb(4) | kpts(10) | score(1)] * keep, float4 stores =====
    float4* out4 = (float4*)(out + (size_t)b * KK * 15);
    for (int e4 = tid; e4 < (KK * 15) / 4; e4 += NT) {
        float r[4];
        #pragma unroll
        for (int q = 0; q < 4; q++) {
            int e = e4 * 4 + q;
            int row = e / 15;
            int c2 = e - row * 15;
            float m = ((s->skept[row >> 6] >> (row & 63)) & 1ull) ? 1.0f : 0.0f;
            float v;
            if (c2 < 4)       v = ((const float*)&s->u.n.sbox[row])[c2];
            else if (c2 < 14) v = s->u.n.skpt[row * 10 + (c2 - 4)];
            else              v = s->u.n.sval[row];
            r[q] = v * m;
        }
        out4[e4] = make_float4(r[0], r[1], r[2], r[3]);
    }
}

extern "C" void kernel_launch(void* const* d_in, const int* in_sizes, int n_in,
                              void* d_out, int out_size) {
    const float* p_loc    = (const float*)d_in[0];
    const float* p_conf   = (const float*)d_in[1];
    const float* p_landms = (const float*)d_in[2];
    const float* anchors  = (const float*)d_in[3];

    cudaFuncSetAttribute(k_fused, cudaFuncAttributeMaxDynamicSharedMemorySize, (int)sizeof(SF));
    k_fused<<<BB, NT, sizeof(SF)>>>(p_loc, p_conf, p_landms, anchors, (float*)d_out);
}